// round 3
// baseline (speedup 1.0000x reference)
#include <cuda_runtime.h>

// Involution2d on GB300 (sm_103a). B=4, C=256, H=W=64, G=16, K=7, PAD=3.
//
// Pre-kernel: transpose w_kernel[784][256] -> g_wt[256][1024]
//             (col = gq*256 + grp*64 + k, taps padded 49->64 with zeros)
// Main kernel: block = (b*64+h, gq), 256 threads, 2 blocks/SM.
//   Stage 1: kern[64px][256 padded taps] = X[64px][256c] * W[256c][256taps]
//            c streamed in 8 chunks of 32, double-buffered cp.async,
//            8x8 register fragments per thread.
//   Stage 2: 49-tap dynamic conv; thread = 4 adjacent px x 4 channels of one
//            group (k values reused 4x from registers), float4 output stores.

#define CH 256
#define HH 64
#define WW 64
#define KT 7
#define KK 49
#define KPAD 64
#define CGQ 4                 // groups per block
#define TAPS 256              // CGQ * KPAD
#define RTAPS 196             // CGQ * KK
#define CC 32                 // channels per chunk
#define NCHUNK 8
#define KSTR 197              // k_s row stride (odd -> conflict-free)
#define WT_STRIDE 1024        // g_wt row stride: 4 quads * 256 padded taps

#define XBUF_F (CC * WW)      // 2048 floats per x buffer
#define WBUF_F (CC * TAPS)    // 8192 floats per w buffer
#define SMEM_FLOATS (2 * XBUF_F + 2 * WBUF_F)   // 20480
#define SMEM_BYTES (SMEM_FLOATS * 4)            // 81920

__device__ float g_wt[CH * WT_STRIDE];          // 1 MB static scratch

// ---------------- w transpose + pad kernel ----------------
__global__ void wt_transpose_kernel(const float* __restrict__ wk) {
    __shared__ float s[32][33];
    const int c0   = blockIdx.x * 32;
    const int col0 = blockIdx.y * 32;
    const int tx = threadIdx.x, ty = threadIdx.y;

    const int col = col0 + ty;
    const int gq  = col >> 8;
    const int rem = col & 255;
    const int grp = rem >> 6;
    const int k   = rem & 63;
    float v = 0.0f;
    if (k < KK) {
        const int r = (gq * 4 + grp) * KK + k;       // row in w_kernel
        v = wk[r * CH + c0 + tx];                    // coalesced read
    }
    s[ty][tx] = v;
    __syncthreads();
    g_wt[(c0 + ty) * WT_STRIDE + col0 + tx] = s[tx][ty];  // coalesced write
}

// ---------------- cp.async helpers ----------------
__device__ __forceinline__ void cp16(float* dst, const float* src) {
    unsigned sa = (unsigned)__cvta_generic_to_shared(dst);
    asm volatile("cp.async.cg.shared.global [%0], [%1], 16;" :: "r"(sa), "l"(src));
}
__device__ __forceinline__ void cp_commit() { asm volatile("cp.async.commit_group;"); }
__device__ __forceinline__ void cp_wait1()  { asm volatile("cp.async.wait_group 1;"); }
__device__ __forceinline__ void cp_wait0()  { asm volatile("cp.async.wait_group 0;"); }

// ---------------- main fused kernel ----------------
__global__ __launch_bounds__(256, 2)
void invo_main_kernel(const float* __restrict__ x,
                      const float* __restrict__ bk,
                      float* __restrict__ out) {
    extern __shared__ float sm[];
    float* xbuf0 = sm;
    float* xbuf1 = sm + XBUF_F;
    float* wbuf0 = sm + 2 * XBUF_F;
    float* wbuf1 = sm + 2 * XBUF_F + WBUF_F;
    float* k_s   = sm;                       // aliases buffers after stage 1

    const int t  = threadIdx.x;
    const int rb = blockIdx.x;
    const int b  = rb >> 6;
    const int h  = rb & 63;
    const int gq = blockIdx.y;

    // ---- chunk loader: x rows c0..c0+31 of row h, and w_t columns for gq ----
    auto load_chunk = [&](int chunk, int pb) {
        const int c0 = chunk * CC;
        float* xb = pb ? xbuf1 : xbuf0;
        float* wb = pb ? wbuf1 : wbuf0;
        #pragma unroll
        for (int u = t; u < XBUF_F / 4; u += 256) {       // 512 units, 2/thread
            const int cc = u >> 4;
            const int w4 = (u & 15) << 2;
            cp16(xb + cc * WW + w4,
                 x + ((size_t)(b * CH + c0 + cc) * HH + h) * WW + w4);
        }
        #pragma unroll
        for (int u = t; u < WBUF_F / 4; u += 256) {       // 2048 units, 8/thread
            const int cc = u >> 6;
            const int t4 = (u & 63) << 2;
            cp16(wb + cc * TAPS + t4,
                 g_wt + (size_t)(c0 + cc) * WT_STRIDE + gq * TAPS + t4);
        }
        cp_commit();
    };

    // ---- Stage 1: 8x8 fragment GEMM over streamed chunks ----
    const int p0  = (t & 7) << 3;    // pixel base 0..56
    const int kq0 = (t >> 3) << 3;   // padded tap base 0..248

    float acc[8][8];
    #pragma unroll
    for (int i = 0; i < 8; ++i)
        #pragma unroll
        for (int j = 0; j < 8; ++j) acc[i][j] = 0.0f;

    load_chunk(0, 0);
    for (int ch = 0; ch < NCHUNK; ++ch) {
        const int pb = ch & 1;
        if (ch + 1 < NCHUNK) { load_chunk(ch + 1, pb ^ 1); cp_wait1(); }
        else                 { cp_wait0(); }
        __syncthreads();

        const float* xb = pb ? xbuf1 : xbuf0;
        const float* wb = pb ? wbuf1 : wbuf0;

        #pragma unroll 2
        for (int cc = 0; cc < CC; ++cc) {
            const float4 xa = *reinterpret_cast<const float4*>(xb + cc * WW + p0);
            const float4 xc = *reinterpret_cast<const float4*>(xb + cc * WW + p0 + 4);
            const float4 wa = *reinterpret_cast<const float4*>(wb + cc * TAPS + kq0);
            const float4 wc = *reinterpret_cast<const float4*>(wb + cc * TAPS + kq0 + 4);
            const float xv[8] = {xa.x, xa.y, xa.z, xa.w, xc.x, xc.y, xc.z, xc.w};
            const float wv[8] = {wa.x, wa.y, wa.z, wa.w, wc.x, wc.y, wc.z, wc.w};
            #pragma unroll
            for (int pi = 0; pi < 8; ++pi)
                #pragma unroll
                for (int ki = 0; ki < 8; ++ki)
                    acc[pi][ki] += xv[pi] * wv[ki];
        }
        __syncthreads();   // guards buffer reuse by next chunk's cp.async
    }

    // ---- epilogue: bias add, write valid taps to k_s (aliases buffers) ----
    {
        const int grp = kq0 >> 6;
        const int kk0 = kq0 & 63;
        #pragma unroll
        for (int ki = 0; ki < 8; ++ki) {
            const int kk = kk0 + ki;
            if (kk < KK) {
                const float bias = bk[(gq * CGQ + grp) * KK + kk];
                #pragma unroll
                for (int pi = 0; pi < 8; ++pi)
                    k_s[(p0 + pi) * KSTR + grp * KK + kk] = acc[pi][ki] + bias;
            }
        }
    }
    __syncthreads();

    // ---- Stage 2: apply per-pixel 7x7 kernels ----
    // thread: 4 adjacent pixels (w0..w0+3) x 4 channels {j, j+4, j+8, j+12} of group grp2
    const int wg   = t & 15;
    const int w0   = wg << 2;
    const int q    = t >> 4;
    const int grp2 = q >> 2;
    const int j    = q & 3;

    float o[4][4];
    #pragma unroll
    for (int m = 0; m < 4; ++m)
        #pragma unroll
        for (int pi = 0; pi < 4; ++pi) o[m][pi] = 0.0f;

    #pragma unroll
    for (int kh = 0; kh < KT; ++kh) {
        const int hh = h + kh - 3;
        if ((unsigned)hh >= (unsigned)HH) continue;

        // per-pixel kernel values for this kh row: reused across 4 channels
        float kv[4][KT];
        #pragma unroll
        for (int pi = 0; pi < 4; ++pi)
            #pragma unroll
            for (int kw = 0; kw < KT; ++kw)
                kv[pi][kw] = k_s[(w0 + pi) * KSTR + grp2 * KK + kh * KT + kw];

        #pragma unroll
        for (int m = 0; m < 4; ++m) {
            const int c = gq * 64 + grp2 * 16 + j + (m << 2);
            const float* xr = x + ((size_t)(b * CH + c) * HH + hh) * WW;
            float xv[10];
            #pragma unroll
            for (int jj = 0; jj < 10; ++jj) {
                const int ww = w0 - 3 + jj;
                xv[jj] = ((unsigned)ww < (unsigned)WW) ? xr[ww] : 0.0f;
            }
            #pragma unroll
            for (int kw = 0; kw < KT; ++kw)
                #pragma unroll
                for (int pi = 0; pi < 4; ++pi)
                    o[m][pi] += xv[pi + kw] * kv[pi][kw];
        }
    }

    #pragma unroll
    for (int m = 0; m < 4; ++m) {
        const int c = gq * 64 + grp2 * 16 + j + (m << 2);
        const float4 r4 = make_float4(o[m][0], o[m][1], o[m][2], o[m][3]);
        *reinterpret_cast<float4*>(out + ((size_t)(b * CH + c) * HH + h) * WW + w0) = r4;
    }
}

extern "C" void kernel_launch(void* const* d_in, const int* in_sizes, int n_in,
                              void* d_out, int out_size) {
    const float* x  = (const float*)d_in[0];
    const float* wk = (const float*)d_in[1];
    const float* bk = (const float*)d_in[2];
    float* out      = (float*)d_out;

    // 1) transpose + pad weights into g_wt
    dim3 tb(32, 32);
    dim3 tg(CH / 32, WT_STRIDE / 32);   // (8, 32)
    wt_transpose_kernel<<<tg, tb>>>(wk);

    // 2) fused involution
    cudaFuncSetAttribute(invo_main_kernel,
                         cudaFuncAttributeMaxDynamicSharedMemorySize, SMEM_BYTES);
    dim3 grid(4 * HH, CGQ);             // (256, 4) = 1024 blocks
    invo_main_kernel<<<grid, 256, SMEM_BYTES>>>(x, bk, out);
}

// round 5
// speedup vs baseline: 1.4326x; 1.4326x over previous
#include <cuda_runtime.h>
#include <cstdint>

// Involution2d on GB300 (sm_103a built as sm_103 base ISA).
// B=4, C=256, H=W=64, G=16, K=7, PAD=3.
// Stage 1 = mma.sync.m16n8k8 tf32 (tensor cores), stage 2 = fp32 conv.

#define CH 256
#define HH 64
#define WW 64
#define KT 7
#define KK 49
#define CC 32                 // channels per chunk
#define NCHUNK 8
#define TAPS 256              // 4 groups * 64 padded taps
#define KSTR 197
#define WT_STRIDE 1024

#define XBUF_F (CC * WW)      // 2048 floats
#define WBUF_F (CC * TAPS)    // 8192 floats
#define SMEM_FLOATS (2 * XBUF_F + 2 * WBUF_F)   // 20480
#define SMEM_BYTES (SMEM_FLOATS * 4)            // 81920

__device__ float g_wt[CH * WT_STRIDE];          // [c][gq*256 + grp*64 + k], tf32

// ---------------- helpers ----------------
__device__ __forceinline__ uint32_t f2tf32u(float x) {
    uint32_t u;
    asm("cvt.rn.tf32.f32 %0, %1;" : "=r"(u) : "f"(x));
    return u;
}
__device__ __forceinline__ void cp16(float* dst, const float* src) {
    unsigned sa = (unsigned)__cvta_generic_to_shared(dst);
    asm volatile("cp.async.cg.shared.global [%0], [%1], 16;" :: "r"(sa), "l"(src));
}
__device__ __forceinline__ void cp_commit() { asm volatile("cp.async.commit_group;"); }
__device__ __forceinline__ void cp_wait1()  { asm volatile("cp.async.wait_group 1;"); }
__device__ __forceinline__ void cp_wait0()  { asm volatile("cp.async.wait_group 0;"); }

__device__ __forceinline__ void mma8(float* c, const uint32_t* a, const uint32_t* b) {
    asm volatile(
        "mma.sync.aligned.m16n8k8.row.col.f32.tf32.tf32.f32 "
        "{%0,%1,%2,%3}, {%4,%5,%6,%7}, {%8,%9}, {%0,%1,%2,%3};"
        : "+f"(c[0]), "+f"(c[1]), "+f"(c[2]), "+f"(c[3])
        : "r"(a[0]), "r"(a[1]), "r"(a[2]), "r"(a[3]), "r"(b[0]), "r"(b[1]));
}

// ---------------- w transpose + pad + tf32 round ----------------
__global__ void wt_transpose_kernel(const float* __restrict__ wk) {
    __shared__ float s[32][33];
    const int c0   = blockIdx.x * 32;
    const int col0 = blockIdx.y * 32;
    const int tx = threadIdx.x, ty = threadIdx.y;

    const int col = col0 + ty;
    const int gq  = col >> 8;
    const int rem = col & 255;
    const int grp = rem >> 6;
    const int k   = rem & 63;
    float v = 0.0f;
    if (k < KK) {
        const int r = (gq * 4 + grp) * KK + k;
        v = __uint_as_float(f2tf32u(wk[r * CH + c0 + tx]));
    }
    s[ty][tx] = v;
    __syncthreads();
    g_wt[(c0 + ty) * WT_STRIDE + col0 + tx] = s[tx][ty];
}

// ---------------- fused main kernel ----------------
__global__ __launch_bounds__(256, 2)
void invo_main_kernel(const float* __restrict__ x,
                      const float* __restrict__ bk,
                      float* __restrict__ out) {
    extern __shared__ float sm[];
    float* xbuf0 = sm;
    float* xbuf1 = sm + XBUF_F;
    float* wbuf0 = sm + 2 * XBUF_F;
    float* wbuf1 = sm + 2 * XBUF_F + WBUF_F;
    float* k_s   = sm;                       // aliases buffers after stage 1

    const int t  = threadIdx.x;
    const int rb = blockIdx.x;
    const int b  = rb >> 6;
    const int h  = rb & 63;
    const int gq = blockIdx.y;

    // ---- chunk loader with XOR-swizzled smem layout ----
    // A: x_s[k][px64], float idx = k*64 + (px ^ (8*(k&3)))
    // B: w_s[k][256],  float idx = k*256 + (n ^ (8*(k&3)))
    auto load_chunk = [&](int chunk, int pb) {
        const int c0 = chunk * CC;
        float* xb = pb ? xbuf1 : xbuf0;
        float* wb = pb ? wbuf1 : wbuf0;
        #pragma unroll
        for (int i = 0; i < 2; ++i) {                 // 512 cp16
            const int u = t + 256 * i;
            const int k = u >> 4;
            const int p4 = (u & 15) << 2;
            cp16(xb + k * 64 + (p4 ^ (8 * (k & 3))),
                 x + ((size_t)(b * CH + c0 + k) * HH + h) * WW + p4);
        }
        #pragma unroll
        for (int i = 0; i < 8; ++i) {                 // 2048 cp16
            const int u = t + 256 * i;
            const int k = u >> 6;
            const int n4 = (u & 63) << 2;
            cp16(wb + k * 256 + (n4 ^ (8 * (k & 3))),
                 g_wt + (size_t)(c0 + k) * WT_STRIDE + gq * 256 + n4);
        }
        cp_commit();
    };

    // ---- Stage 1: mma.sync tf32, warp tile m32 x n64 ----
    const int wid  = t >> 5, lane = t & 31;
    const int la   = lane & 3, gid = lane >> 2;
    const int m0w  = (wid & 1) * 32;        // pixel base
    const int n0w  = (wid >> 1) * 64;       // tap base (= group (wid>>1))
    const int sw   = 8 * la;

    float acc[2][8][4];
    #pragma unroll
    for (int mt = 0; mt < 2; ++mt)
        #pragma unroll
        for (int nt = 0; nt < 8; ++nt)
            #pragma unroll
            for (int i = 0; i < 4; ++i) acc[mt][nt][i] = 0.0f;

    load_chunk(0, 0);
    for (int ch = 0; ch < NCHUNK; ++ch) {
        const int pb = ch & 1;
        if (ch + 1 < NCHUNK) { load_chunk(ch + 1, pb ^ 1); cp_wait1(); }
        else                 { cp_wait0(); }
        __syncthreads();

        const float* xb = pb ? xbuf1 : xbuf0;
        const float* wb = pb ? wbuf1 : wbuf0;

        #pragma unroll
        for (int ks = 0; ks < 4; ++ks) {
            const int kb = ks * 8;
            // A fragments (cvt.rn.tf32 at load)
            uint32_t af[2][4];
            #pragma unroll
            for (int mt = 0; mt < 2; ++mt) {
                const int rm = m0w + mt * 16;
                const int r0 = (rm + gid) ^ sw;
                const int r1 = (rm + 8 + gid) ^ sw;
                af[mt][0] = f2tf32u(xb[(kb + la) * 64 + r0]);
                af[mt][1] = f2tf32u(xb[(kb + la) * 64 + r1]);
                af[mt][2] = f2tf32u(xb[(kb + la + 4) * 64 + r0]);
                af[mt][3] = f2tf32u(xb[(kb + la + 4) * 64 + r1]);
            }
            // B fragments (pre-rounded tf32)
            #pragma unroll
            for (int nt = 0; nt < 8; ++nt) {
                const int cn = (n0w + nt * 8 + gid) ^ sw;
                uint32_t bf[2];
                bf[0] = __float_as_uint(wb[(kb + la) * 256 + cn]);
                bf[1] = __float_as_uint(wb[(kb + la + 4) * 256 + cn]);
                mma8(acc[0][nt], af[0], bf);
                mma8(acc[1][nt], af[1], bf);
            }
        }
        __syncthreads();   // buffers free for next chunk's cp.async
    }

    // ---- epilogue: bias add, write valid taps to k_s[px][grp*49+kk] ----
    {
        const int grp = wid >> 1;
        #pragma unroll
        for (int mt = 0; mt < 2; ++mt) {
            const int px0 = m0w + mt * 16 + gid;
            #pragma unroll
            for (int nt = 0; nt < 8; ++nt) {
                const int kk = nt * 8 + la * 2;
                if (kk < KK) {
                    const float bias = bk[(gq * 4 + grp) * KK + kk];
                    k_s[px0 * KSTR + grp * KK + kk]       = acc[mt][nt][0] + bias;
                    k_s[(px0 + 8) * KSTR + grp * KK + kk] = acc[mt][nt][2] + bias;
                }
                if (kk + 1 < KK) {
                    const float bias1 = bk[(gq * 4 + grp) * KK + kk + 1];
                    k_s[px0 * KSTR + grp * KK + kk + 1]       = acc[mt][nt][1] + bias1;
                    k_s[(px0 + 8) * KSTR + grp * KK + kk + 1] = acc[mt][nt][3] + bias1;
                }
            }
        }
    }
    __syncthreads();

    // ---- Stage 2: apply per-pixel 7x7 kernels (fp32, unchanged from R2) ----
    const int wg   = t & 15;
    const int w0   = wg << 2;
    const int q    = t >> 4;
    const int grp2 = q >> 2;
    const int j    = q & 3;

    float o[4][4];
    #pragma unroll
    for (int m = 0; m < 4; ++m)
        #pragma unroll
        for (int pi = 0; pi < 4; ++pi) o[m][pi] = 0.0f;

    #pragma unroll
    for (int kh = 0; kh < KT; ++kh) {
        const int hh = h + kh - 3;
        if ((unsigned)hh >= (unsigned)HH) continue;

        float kv[4][KT];
        #pragma unroll
        for (int pi = 0; pi < 4; ++pi)
            #pragma unroll
            for (int kw = 0; kw < KT; ++kw)
                kv[pi][kw] = k_s[(w0 + pi) * KSTR + grp2 * KK + kh * KT + kw];

        #pragma unroll
        for (int m = 0; m < 4; ++m) {
            const int c = gq * 64 + grp2 * 16 + j + (m << 2);
            const float* xr = x + ((size_t)(b * CH + c) * HH + hh) * WW;
            float xv[10];
            #pragma unroll
            for (int jj = 0; jj < 10; ++jj) {
                const int ww = w0 - 3 + jj;
                xv[jj] = ((unsigned)ww < (unsigned)WW) ? xr[ww] : 0.0f;
            }
            #pragma unroll
            for (int kw = 0; kw < KT; ++kw)
                #pragma unroll
                for (int pi = 0; pi < 4; ++pi)
                    o[m][pi] += xv[pi + kw] * kv[pi][kw];
        }
    }

    #pragma unroll
    for (int m = 0; m < 4; ++m) {
        const int c = gq * 64 + grp2 * 16 + j + (m << 2);
        *reinterpret_cast<float4*>(out + ((size_t)(b * CH + c) * HH + h) * WW + w0) =
            make_float4(o[m][0], o[m][1], o[m][2], o[m][3]);
    }
}

extern "C" void kernel_launch(void* const* d_in, const int* in_sizes, int n_in,
                              void* d_out, int out_size) {
    const float* x  = (const float*)d_in[0];
    const float* wk = (const float*)d_in[1];
    const float* bk = (const float*)d_in[2];
    float* out      = (float*)d_out;

    dim3 tb(32, 32);
    dim3 tg(CH / 32, WT_STRIDE / 32);
    wt_transpose_kernel<<<tg, tb>>>(wk);

    cudaFuncSetAttribute(invo_main_kernel,
                         cudaFuncAttributeMaxDynamicSharedMemorySize, SMEM_BYTES);
    dim3 grid(4 * HH, 4);               // (256, 4) = 1024 blocks
    invo_main_kernel<<<grid, 256, SMEM_BYTES>>>(x, bk, out);
}

// round 7
// speedup vs baseline: 2.7146x; 1.8949x over previous
#include <cuda_runtime.h>
#include <cstdint>

// Involution2d on GB300 (sm_103 base ISA). B=4, C=256, H=W=64, G=16, K=7, PAD=3.
// Stage 1 = mma.sync.m16n8k8 tf32, stage 2 = fp32 conv.
// Block = (b, h-pair, gq): 512 threads, 2 output rows, 4 groups.

#define CH 256
#define HH 64
#define WW 64
#define KT 7
#define KK 49
#define CC 64                  // channels per chunk
#define NCHUNK 4
#define TAPS 256               // 4 groups * 64 padded taps
#define WT_STRIDE 1024
#define PX 128                 // pixels per block (2 rows)
#define KROW 132               // k_s row stride (slot-major), 132%32=4 -> conflict-free

#define XBUF_F (CC * PX)       // 8192 floats
#define WBUF_F (CC * TAPS)     // 16384 floats
#define SMEM_BYTES ((2 * XBUF_F + 2 * WBUF_F) * 4)   // 196608

__device__ float g_wt[CH * WT_STRIDE];   // [c][gq*256 + grp*64 + k], tf32 pre-rounded

// ---------------- helpers ----------------
__device__ __forceinline__ uint32_t f2tf32u(float x) {
    uint32_t u;
    asm("cvt.rn.tf32.f32 %0, %1;" : "=r"(u) : "f"(x));
    return u;
}
__device__ __forceinline__ void cp16(float* dst, const float* src) {
    unsigned sa = (unsigned)__cvta_generic_to_shared(dst);
    asm volatile("cp.async.cg.shared.global [%0], [%1], 16;" :: "r"(sa), "l"(src));
}
__device__ __forceinline__ void cp_commit() { asm volatile("cp.async.commit_group;"); }
__device__ __forceinline__ void cp_wait1()  { asm volatile("cp.async.wait_group 1;"); }
__device__ __forceinline__ void cp_wait0()  { asm volatile("cp.async.wait_group 0;"); }

__device__ __forceinline__ void mma8(float* c, const uint32_t* a, const uint32_t* b) {
    asm volatile(
        "mma.sync.aligned.m16n8k8.row.col.f32.tf32.tf32.f32 "
        "{%0,%1,%2,%3}, {%4,%5,%6,%7}, {%8,%9}, {%0,%1,%2,%3};"
        : "+f"(c[0]), "+f"(c[1]), "+f"(c[2]), "+f"(c[3])
        : "r"(a[0]), "r"(a[1]), "r"(a[2]), "r"(a[3]), "r"(b[0]), "r"(b[1]));
}

// ---------------- w transpose + pad + tf32 round ----------------
__global__ void wt_transpose_kernel(const float* __restrict__ wk) {
    __shared__ float s[32][33];
    const int c0 = blockIdx.x * 32, col0 = blockIdx.y * 32;
    const int tx = threadIdx.x, ty = threadIdx.y;
    const int col = col0 + ty;
    const int gq = col >> 8, rem = col & 255;
    const int grp = rem >> 6, k = rem & 63;
    float v = 0.0f;
    if (k < KK) v = __uint_as_float(f2tf32u(wk[((gq * 4 + grp) * KK + k) * CH + c0 + tx]));
    s[ty][tx] = v;
    __syncthreads();
    g_wt[(c0 + ty) * WT_STRIDE + col0 + tx] = s[tx][ty];
}

// ---------------- fused main kernel ----------------
__global__ __launch_bounds__(512, 1)
void invo_main_kernel(const float* __restrict__ x,
                      const float* __restrict__ bk,
                      float* __restrict__ out) {
    extern __shared__ float sm[];
    float* xbuf0 = sm;
    float* xbuf1 = sm + XBUF_F;
    float* wbuf0 = sm + 2 * XBUF_F;
    float* wbuf1 = sm + 2 * XBUF_F + WBUF_F;
    float* k_s   = sm;                      // [slot 196][KROW], aliased after stage 1

    const int t  = threadIdx.x;
    const int rb = blockIdx.x;
    const int b  = rb >> 5;
    const int h  = (rb & 31) * 2;           // rows h, h+1
    const int gq = blockIdx.y;

    // ---- chunk loader ----
    // x_s[k][px128]: elem (k,px) at k*128 + (px ^ 8*(k&3))
    // w_s[k][n256] : elem (k,n)  at k*256 + (n  ^ 8*(k&3))
    auto load_chunk = [&](int chunk, int pb) {
        const int c0 = chunk * CC;
        float* xb = pb ? xbuf1 : xbuf0;
        float* wb = pb ? wbuf1 : wbuf0;
        #pragma unroll
        for (int i = 0; i < 4; ++i) {                 // 2048 cp16
            const int u = t + 512 * i;
            const int k = u >> 5;
            const int p4 = (u & 31) << 2;
            cp16(xb + k * PX + (p4 ^ (8 * (k & 3))),
                 x + ((size_t)(b * CH + c0 + k)) * 4096 + h * 64 + p4);
        }
        #pragma unroll
        for (int i = 0; i < 8; ++i) {                 // 4096 cp16
            const int u = t + 512 * i;
            const int k = u >> 6;
            const int n4 = (u & 63) << 2;
            cp16(wb + k * TAPS + (n4 ^ (8 * (k & 3))),
                 g_wt + (size_t)(c0 + k) * WT_STRIDE + gq * 256 + n4);
        }
        cp_commit();
    };

    // ---- Stage 1: mma.sync tf32, 16 warps, warp tile m32 x n64 ----
    const int wid = t >> 5, lane = t & 31;
    const int la = lane & 3, gid = lane >> 2;
    const int mq = wid & 3, nq = wid >> 2;
    const int m0w = mq * 32;                // pixel base (0..96)
    const int n0w = nq * 64;                // tap base = group nq
    const int sw = 8 * la;

    float acc[2][8][4];
    #pragma unroll
    for (int mt = 0; mt < 2; ++mt)
        #pragma unroll
        for (int nt = 0; nt < 8; ++nt)
            #pragma unroll
            for (int i = 0; i < 4; ++i) acc[mt][nt][i] = 0.0f;

    load_chunk(0, 0);
    for (int ch = 0; ch < NCHUNK; ++ch) {
        const int pb = ch & 1;
        if (ch + 1 < NCHUNK) { load_chunk(ch + 1, pb ^ 1); cp_wait1(); }
        else                 { cp_wait0(); }
        __syncthreads();

        const float* xb = pb ? xbuf1 : xbuf0;
        const float* wb = pb ? wbuf1 : wbuf0;

        #pragma unroll
        for (int ks = 0; ks < 8; ++ks) {
            const int kb = ks * 8;
            uint32_t af[2][4];
            #pragma unroll
            for (int mt = 0; mt < 2; ++mt) {
                const int rm = m0w + mt * 16;
                const int r0 = (rm + gid) ^ sw;
                const int r1 = (rm + 8 + gid) ^ sw;
                af[mt][0] = f2tf32u(xb[(kb + la) * PX + r0]);
                af[mt][1] = f2tf32u(xb[(kb + la) * PX + r1]);
                af[mt][2] = f2tf32u(xb[(kb + la + 4) * PX + r0]);
                af[mt][3] = f2tf32u(xb[(kb + la + 4) * PX + r1]);
            }
            #pragma unroll
            for (int nt = 0; nt < 8; ++nt) {
                const int cn = (n0w + nt * 8 + gid) ^ sw;
                uint32_t bf[2];
                bf[0] = __float_as_uint(wb[(kb + la) * TAPS + cn]);
                bf[1] = __float_as_uint(wb[(kb + la + 4) * TAPS + cn]);
                mma8(acc[0][nt], af[0], bf);
                mma8(acc[1][nt], af[1], bf);
            }
        }
        __syncthreads();
    }

    // ---- epilogue: bias add, write k_s[slot = nq*49+kk][px] ----
    // acc[0] rows = m0w+gid (c0/c1), m0w+8+gid (c2/c3)
    // acc[1] rows = m0w+16+gid,      m0w+24+gid
    {
        const int px0 = m0w + gid;
        #pragma unroll
        for (int nt = 0; nt < 8; ++nt) {
            const int kk = nt * 8 + la * 2;
            if (kk < KK) {
                const float bias = bk[(gq * 4 + nq) * KK + kk];
                const int s = nq * KK + kk;
                k_s[s * KROW + px0]      = acc[0][nt][0] + bias;
                k_s[s * KROW + px0 + 8]  = acc[0][nt][2] + bias;
                k_s[s * KROW + px0 + 16] = acc[1][nt][0] + bias;
                k_s[s * KROW + px0 + 24] = acc[1][nt][2] + bias;
            }
            if (kk + 1 < KK) {
                const float bias1 = bk[(gq * 4 + nq) * KK + kk + 1];
                const int s1 = nq * KK + kk + 1;
                k_s[s1 * KROW + px0]      = acc[0][nt][1] + bias1;
                k_s[s1 * KROW + px0 + 8]  = acc[0][nt][3] + bias1;
                k_s[s1 * KROW + px0 + 16] = acc[1][nt][1] + bias1;
                k_s[s1 * KROW + px0 + 24] = acc[1][nt][3] + bias1;
            }
        }
    }
    __syncthreads();

    // ---- Stage 2: apply per-pixel 7x7 kernels (fp32) ----
    const int pxg  = t & 15, w0 = pxg << 2;
    const int q    = (t >> 4) & 15;
    const int grp2 = q >> 2, chq = q & 3;
    const int hrow = t >> 8;
    const int hout = h + hrow;

    float o[4][4];
    #pragma unroll
    for (int m = 0; m < 4; ++m)
        #pragma unroll
        for (int pi = 0; pi < 4; ++pi) o[m][pi] = 0.0f;

    #pragma unroll
    for (int kh = 0; kh < KT; ++kh) {
        const int hh = hout + kh - 3;
        if ((unsigned)hh >= (unsigned)HH) continue;

        // per-pixel kernel values: conflict-free LDS.128
        float4 kvf[KT];
        #pragma unroll
        for (int kw = 0; kw < KT; ++kw)
            kvf[kw] = *(const float4*)&k_s[(grp2 * KK + kh * KT + kw) * KROW + hrow * 64 + w0];

        #pragma unroll
        for (int m = 0; m < 4; ++m) {
            const int c = gq * 64 + grp2 * 16 + chq + (m << 2);
            const float* xr = x + ((size_t)(b * CH + c) * HH + hh) * WW;
            const float4 A = (pxg >= 1)  ? *(const float4*)(xr + w0 - 4)
                                         : make_float4(0.f, 0.f, 0.f, 0.f);
            const float4 Bv = *(const float4*)(xr + w0);
            const float4 Cc = (pxg <= 14) ? *(const float4*)(xr + w0 + 4)
                                          : make_float4(0.f, 0.f, 0.f, 0.f);
            const float xv[10] = {A.y, A.z, A.w, Bv.x, Bv.y, Bv.z, Bv.w, Cc.x, Cc.y, Cc.z};
            #pragma unroll
            for (int kw = 0; kw < KT; ++kw) {
                o[m][0] += xv[kw]     * kvf[kw].x;
                o[m][1] += xv[kw + 1] * kvf[kw].y;
                o[m][2] += xv[kw + 2] * kvf[kw].z;
                o[m][3] += xv[kw + 3] * kvf[kw].w;
            }
        }
    }

    #pragma unroll
    for (int m = 0; m < 4; ++m) {
        const int c = gq * 64 + grp2 * 16 + chq + (m << 2);
        *reinterpret_cast<float4*>(out + ((size_t)(b * CH + c) * HH + hout) * WW + w0) =
            make_float4(o[m][0], o[m][1], o[m][2], o[m][3]);
    }
}

extern "C" void kernel_launch(void* const* d_in, const int* in_sizes, int n_in,
                              void* d_out, int out_size) {
    const float* x  = (const float*)d_in[0];
    const float* wk = (const float*)d_in[1];
    const float* bk = (const float*)d_in[2];
    float* out      = (float*)d_out;

    dim3 tb(32, 32);
    dim3 tg(CH / 32, WT_STRIDE / 32);
    wt_transpose_kernel<<<tg, tb>>>(wk);

    cudaFuncSetAttribute(invo_main_kernel,
                         cudaFuncAttributeMaxDynamicSharedMemorySize, SMEM_BYTES);
    dim3 grid(4 * 32, 4);               // (b*hpair, gq) = (128, 4) = 512 blocks
    invo_main_kernel<<<grid, 512, SMEM_BYTES>>>(x, bk, out);
}